// round 1
// baseline (speedup 1.0000x reference)
#include <cuda_runtime.h>
#include <cuda_bf16.h>
#include <math.h>

#define Nn  20000
#define Ee  80000
#define Hh  64
#define NFf 32
#define Bb  64
#define HID 128

// ---------------- device scratch (no allocations allowed) ----------------
__device__ float g_X[Nn * Hh];            // node state (out == h)
__device__ float g_agg[Nn * Hh];          // scatter accumulator
__device__ float g_hid[Ee * HID];         // edge MLP hidden
__device__ float g_we[(size_t)Ee * Hh * Hh]; // 1.31 GB edge weights
__device__ float g_deg[Nn];
__device__ int   g_cnt[Bb];
__device__ int   g_ptr[Bb + 1];
__device__ float g_en[Nn];
__device__ float g_hs[Bb * Hh];
__device__ float g_cs[Bb * Hh];
__device__ float g_qstar[Bb * 2 * Hh];

__device__ __forceinline__ float sigf(float x) { return 1.0f / (1.0f + expf(-x)); }

// ---------------- lin0: X = relu(x @ W0 + b0) ----------------
__global__ void k_lin0(const float* __restrict__ x, const float* __restrict__ w,
                       const float* __restrict__ b) {
    __shared__ float xs[NFf];
    int n = blockIdx.x, o = threadIdx.x;           // 64 threads
    if (o < NFf) xs[o] = x[n * NFf + o];
    __syncthreads();
    float acc = b[o];
#pragma unroll
    for (int i = 0; i < NFf; i++) acc = fmaf(xs[i], w[i * Hh + o], acc);
    g_X[n * Hh + o] = fmaxf(acc, 0.0f);
}

// ---------------- edge MLP layer 1: hid = relu(edge_attr @ W1 + b1) ----------------
__global__ void k_mlp1(const float* __restrict__ ea, const float* __restrict__ w,
                       const float* __restrict__ b) {
    __shared__ float es[Hh];
    int e = blockIdx.x, j = threadIdx.x;           // 128 threads
    if (j < Hh) es[j] = ea[e * Hh + j];
    __syncthreads();
    float acc = b[j];
#pragma unroll
    for (int i = 0; i < Hh; i++) acc = fmaf(es[i], w[i * HID + j], acc);
    g_hid[e * HID + j] = fmaxf(acc, 0.0f);
}

// ---------------- big GEMM: we = hid @ W2 + b2   [80000,128]x[128,4096] ----------------
#define BM 64
#define BN 64
#define BK 16
__global__ void k_gemm_we(const float* __restrict__ Bw, const float* __restrict__ bias) {
    __shared__ float As[BK][BM + 4];
    __shared__ float Bs[BK][BN];
    int bn = blockIdx.x;           // 0..63
    int bm = blockIdx.y;           // 0..1249
    int t  = threadIdx.x;          // 256
    int tx = t & 15, ty = t >> 4;
    int arow = t >> 2, aq = t & 3;
    int brow = t >> 4, bq = t & 15;
    const float* A = g_hid + (size_t)bm * BM * HID;
    const float* Bb2 = Bw + bn * BN;
    float acc[4][4] = {};
    for (int kt = 0; kt < HID; kt += BK) {
        float4 av = *(const float4*)&A[arow * HID + kt + aq * 4];
        As[aq * 4 + 0][arow] = av.x; As[aq * 4 + 1][arow] = av.y;
        As[aq * 4 + 2][arow] = av.z; As[aq * 4 + 3][arow] = av.w;
        float4 bv = *(const float4*)&Bb2[(size_t)(kt + brow) * (Hh * Hh) + bq * 4];
        *(float4*)&Bs[brow][bq * 4] = bv;
        __syncthreads();
#pragma unroll
        for (int k = 0; k < BK; k++) {
            float ar[4];
#pragma unroll
            for (int j = 0; j < 4; j++) ar[j] = As[k][ty * 4 + j];
            float4 b4 = *(float4*)&Bs[k][tx * 4];
            float br[4] = {b4.x, b4.y, b4.z, b4.w};
#pragma unroll
            for (int ii = 0; ii < 4; ii++)
#pragma unroll
                for (int jj = 0; jj < 4; jj++)
                    acc[ii][jj] = fmaf(ar[ii], br[jj], acc[ii][jj]);
        }
        __syncthreads();
    }
    float* C = g_we + (size_t)bm * BM * (Hh * Hh) + bn * BN;
    int c0 = bn * BN + tx * 4;
#pragma unroll
    for (int ii = 0; ii < 4; ii++) {
        int r = ty * 4 + ii;
        float4 ov;
        ov.x = acc[ii][0] + bias[c0 + 0];
        ov.y = acc[ii][1] + bias[c0 + 1];
        ov.z = acc[ii][2] + bias[c0 + 2];
        ov.w = acc[ii][3] + bias[c0 + 3];
        *(float4*)&C[(size_t)r * (Hh * Hh) + tx * 4] = ov;
    }
}

// ---------------- degree / batch counts ----------------
__global__ void k_deg(const int* __restrict__ dst) {
    int e = blockIdx.x * blockDim.x + threadIdx.x;
    if (e < Ee) atomicAdd(&g_deg[dst[e]], 1.0f);
}
__global__ void k_cnt(const int* __restrict__ batch) {
    int n = blockIdx.x * blockDim.x + threadIdx.x;
    if (n < Nn) atomicAdd(&g_cnt[batch[n]], 1);
}
__global__ void k_scan() {
    if (threadIdx.x == 0) {
        g_ptr[0] = 0;
        for (int b = 0; b < Bb; b++) g_ptr[b + 1] = g_ptr[b] + g_cnt[b];
    }
}

// ---------------- per-edge matvec + scatter: agg[dst] += X[src] @ we[e] ----------------
__global__ void k_msg(const int* __restrict__ src, const int* __restrict__ dst) {
    __shared__ float xs[Hh];
    int e = blockIdx.x, o = threadIdx.x;           // 64 threads
    int s = src[e], d = dst[e];
    xs[o] = g_X[s * Hh + o];
    __syncthreads();
    const float* we = g_we + (size_t)e * Hh * Hh;
    float acc = 0.0f;
#pragma unroll
    for (int i = 0; i < Hh; i++) acc = fmaf(xs[i], we[i * Hh + o], acc);
    atomicAdd(&g_agg[d * Hh + o], acc);
}

// ---------------- fused m = relu(agg/deg + X@root + cb) ; X = GRU(m, X) ----------------
__global__ void k_gru(const float* __restrict__ cr, const float* __restrict__ cb,
                      const float* __restrict__ wih, const float* __restrict__ whh,
                      const float* __restrict__ bih, const float* __restrict__ bhh) {
    __shared__ float xs[Hh], ms[Hh], gi[3 * Hh], gh[3 * Hh];
    int n = blockIdx.x, t = threadIdx.x;           // 192 threads
    if (t < Hh) xs[t] = g_X[n * Hh + t];
    __syncthreads();
    if (t < Hh) {
        float d = fmaxf(g_deg[n], 1.0f);
        float acc = g_agg[n * Hh + t] / d + cb[t];
#pragma unroll
        for (int i = 0; i < Hh; i++) acc = fmaf(xs[i], cr[i * Hh + t], acc);
        ms[t] = fmaxf(acc, 0.0f);
    }
    __syncthreads();
    {
        float a = bih[t], c = bhh[t];
#pragma unroll
        for (int i = 0; i < Hh; i++) {
            a = fmaf(ms[i], wih[i * 3 * Hh + t], a);
            c = fmaf(xs[i], whh[i * 3 * Hh + t], c);
        }
        gi[t] = a; gh[t] = c;
    }
    __syncthreads();
    if (t < Hh) {
        float r = sigf(gi[t] + gh[t]);
        float z = sigf(gi[Hh + t] + gh[Hh + t]);
        float ng = tanhf(gi[2 * Hh + t] + r * gh[2 * Hh + t]);
        g_X[n * Hh + t] = (1.0f - z) * ng + z * xs[t];
    }
}

// ---------------- Set2Set LSTM step (writes hs, cs, qstar[:,0:64]=h) ----------------
__global__ void k_lstm(const float* __restrict__ wih, const float* __restrict__ whh,
                       const float* __restrict__ bih, const float* __restrict__ bhh) {
    __shared__ float qs[2 * Hh], hr[Hh], g[4 * Hh];
    int b = blockIdx.x, t = threadIdx.x;           // 256 threads
    if (t < 2 * Hh) qs[t] = g_qstar[b * 2 * Hh + t];
    if (t < Hh) hr[t] = g_hs[b * Hh + t];
    __syncthreads();
    {
        float a = bih[t] + bhh[t];
#pragma unroll
        for (int i = 0; i < 2 * Hh; i++) a = fmaf(qs[i], wih[i * 4 * Hh + t], a);
#pragma unroll
        for (int i = 0; i < Hh; i++) a = fmaf(hr[i], whh[i * 4 * Hh + t], a);
        g[t] = a;
    }
    __syncthreads();
    if (t < Hh) {
        float ii = sigf(g[t]);
        float ff = sigf(g[Hh + t]);
        float gg = tanhf(g[2 * Hh + t]);
        float oo = sigf(g[3 * Hh + t]);
        float c2 = ff * g_cs[b * Hh + t] + ii * gg;
        float h2 = oo * tanhf(c2);
        g_cs[b * Hh + t] = c2;
        g_hs[b * Hh + t] = h2;
        g_qstar[b * 2 * Hh + t] = h2;  // q half of q_star
    }
}

// ---------------- en[n] = dot(X[n], hs[batch[n]]) ----------------
__global__ void k_en(const int* __restrict__ batch) {
    __shared__ float red[2];
    int n = blockIdx.x, o = threadIdx.x;           // 64 threads
    int b = batch[n];
    float v = g_X[n * Hh + o] * g_hs[b * Hh + o];
#pragma unroll
    for (int s = 16; s > 0; s >>= 1) v += __shfl_down_sync(0xffffffffu, v, s);
    if ((o & 31) == 0) red[o >> 5] = v;
    __syncthreads();
    if (o == 0) g_en[n] = red[0] + red[1];
}

// ---------------- per-graph softmax + weighted readout r -> qstar[:,64:128] ----------------
__global__ void k_pool() {
    __shared__ float sm[Hh];
    int b = blockIdx.x, t = threadIdx.x;           // 64 threads
    int s = g_ptr[b], e = g_ptr[b + 1];
    // pass 1: max
    float m = -1e30f;
    for (int n = s + t; n < e; n += Hh) m = fmaxf(m, g_en[n]);
    sm[t] = m; __syncthreads();
    for (int st = 32; st > 0; st >>= 1) { if (t < st) sm[t] = fmaxf(sm[t], sm[t + st]); __syncthreads(); }
    float mx = sm[0]; __syncthreads();
    // pass 2: sum exp
    float ss = 0.0f;
    for (int n = s + t; n < e; n += Hh) ss += expf(g_en[n] - mx);
    sm[t] = ss; __syncthreads();
    for (int st = 32; st > 0; st >>= 1) { if (t < st) sm[t] += sm[t + st]; __syncthreads(); }
    float inv = 1.0f / (sm[0] + 1e-16f);
    // pass 3: r[b, t] = sum_n a_n * X[n, t]
    float acc = 0.0f;
    for (int n = s; n < e; n++) {
        float a = expf(g_en[n] - mx) * inv;
        acc = fmaf(a, g_X[n * Hh + t], acc);
    }
    g_qstar[b * 2 * Hh + Hh + t] = acc;
}

// ---------------- head: out[b] = relu(qstar @ W1 + b1) @ W2 + b2 ----------------
__global__ void k_final(const float* __restrict__ w1, const float* __restrict__ b1,
                        const float* __restrict__ w2, const float* __restrict__ b2,
                        float* __restrict__ out) {
    __shared__ float qs[2 * Hh], red[Hh];
    int b = blockIdx.x, t = threadIdx.x;           // 64 threads
    qs[t] = g_qstar[b * 2 * Hh + t];
    qs[Hh + t] = g_qstar[b * 2 * Hh + Hh + t];
    __syncthreads();
    float a = b1[t];
#pragma unroll
    for (int i = 0; i < 2 * Hh; i++) a = fmaf(qs[i], w1[i * Hh + t], a);
    a = fmaxf(a, 0.0f);
    red[t] = a * w2[t];
    __syncthreads();
    for (int st = 32; st > 0; st >>= 1) { if (t < st) red[t] += red[t + st]; __syncthreads(); }
    if (t == 0) out[b] = red[0] + b2[0];
}

// ---------------- launcher ----------------
extern "C" void kernel_launch(void* const* d_in, const int* in_sizes, int n_in,
                              void* d_out, int out_size) {
    const float* x         = (const float*)d_in[0];
    const int*   ei        = (const int*)d_in[1];
    const int*   batch     = (const int*)d_in[2];
    const float* edge_attr = (const float*)d_in[3];
    const float* lin0_w = (const float*)d_in[4];
    const float* lin0_b = (const float*)d_in[5];
    const float* nn_w1  = (const float*)d_in[6];
    const float* nn_b1  = (const float*)d_in[7];
    const float* nn_w2  = (const float*)d_in[8];
    const float* nn_b2  = (const float*)d_in[9];
    const float* conv_root = (const float*)d_in[10];
    const float* conv_bias = (const float*)d_in[11];
    const float* gru_wih = (const float*)d_in[12];
    const float* gru_whh = (const float*)d_in[13];
    const float* gru_bih = (const float*)d_in[14];
    const float* gru_bhh = (const float*)d_in[15];
    const float* lstm_wih = (const float*)d_in[16];
    const float* lstm_whh = (const float*)d_in[17];
    const float* lstm_bih = (const float*)d_in[18];
    const float* lstm_bhh = (const float*)d_in[19];
    const float* lin1_w = (const float*)d_in[20];
    const float* lin1_b = (const float*)d_in[21];
    const float* lin2_w = (const float*)d_in[22];
    const float* lin2_b = (const float*)d_in[23];

    const int* src = ei;
    const int* dst = ei + Ee;

    void *p_agg, *p_deg, *p_cnt, *p_hs, *p_cs, *p_qs;
    cudaGetSymbolAddress(&p_agg, g_agg);
    cudaGetSymbolAddress(&p_deg, g_deg);
    cudaGetSymbolAddress(&p_cnt, g_cnt);
    cudaGetSymbolAddress(&p_hs,  g_hs);
    cudaGetSymbolAddress(&p_cs,  g_cs);
    cudaGetSymbolAddress(&p_qs,  g_qstar);

    cudaMemsetAsync(p_deg, 0, Nn * sizeof(float), 0);
    cudaMemsetAsync(p_cnt, 0, Bb * sizeof(int), 0);
    cudaMemsetAsync(p_hs,  0, Bb * Hh * sizeof(float), 0);
    cudaMemsetAsync(p_cs,  0, Bb * Hh * sizeof(float), 0);
    cudaMemsetAsync(p_qs,  0, Bb * 2 * Hh * sizeof(float), 0);

    k_lin0<<<Nn, Hh>>>(x, lin0_w, lin0_b);
    k_mlp1<<<Ee, HID>>>(edge_attr, nn_w1, nn_b1);
    k_gemm_we<<<dim3((Hh * Hh) / BN, Ee / BM), 256>>>(nn_w2, nn_b2);
    k_deg<<<(Ee + 255) / 256, 256>>>(dst);
    k_cnt<<<(Nn + 255) / 256, 256>>>(batch);
    k_scan<<<1, 32>>>();

    for (int it = 0; it < 3; it++) {
        cudaMemsetAsync(p_agg, 0, Nn * Hh * sizeof(float), 0);
        k_msg<<<Ee, Hh>>>(src, dst);
        k_gru<<<Nn, 3 * Hh>>>(conv_root, conv_bias, gru_wih, gru_whh, gru_bih, gru_bhh);
    }

    for (int st = 0; st < 3; st++) {
        k_lstm<<<Bb, 4 * Hh>>>(lstm_wih, lstm_whh, lstm_bih, lstm_bhh);
        k_en<<<Nn, Hh>>>(batch);
        k_pool<<<Bb, Hh>>>();
    }

    k_final<<<Bb, Hh>>>(lin1_w, lin1_b, lin2_w, lin2_b, (float*)d_out);
}

// round 2
// speedup vs baseline: 1.1164x; 1.1164x over previous
#include <cuda_runtime.h>
#include <cuda_bf16.h>
#include <mma.h>
#include <math.h>

using namespace nvcuda;

#define Nn  20000
#define Ee  80000
#define Hh  64
#define NFf 32
#define Bb  64
#define HID 128

// ---------------- device scratch (no allocations allowed) ----------------
__device__ float g_X[Nn * Hh];            // node state (out == h)
__device__ float g_agg[Nn * Hh];          // scatter accumulator
__device__ float g_hid[Ee * HID];         // edge MLP hidden
__device__ float g_we[(size_t)Ee * Hh * Hh]; // 1.31 GB edge weights
__device__ float g_deg[Nn];
__device__ int   g_cnt[Bb];
__device__ int   g_ptr[Bb + 1];
__device__ float g_en[Nn];
__device__ float g_hs[Bb * Hh];
__device__ float g_cs[Bb * Hh];
__device__ float g_qstar[Bb * 2 * Hh];

__device__ __forceinline__ float sigf(float x) { return 1.0f / (1.0f + expf(-x)); }

// ---------------- lin0: X = relu(x @ W0 + b0) ----------------
__global__ void k_lin0(const float* __restrict__ x, const float* __restrict__ w,
                       const float* __restrict__ b) {
    __shared__ float xs[NFf];
    int n = blockIdx.x, o = threadIdx.x;           // 64 threads
    if (o < NFf) xs[o] = x[n * NFf + o];
    __syncthreads();
    float acc = b[o];
#pragma unroll
    for (int i = 0; i < NFf; i++) acc = fmaf(xs[i], w[i * Hh + o], acc);
    g_X[n * Hh + o] = fmaxf(acc, 0.0f);
}

// ---------------- edge MLP layer 1: hid = relu(edge_attr @ W1 + b1) ----------------
__global__ void k_mlp1(const float* __restrict__ ea, const float* __restrict__ w,
                       const float* __restrict__ b) {
    __shared__ float es[Hh];
    int e = blockIdx.x, j = threadIdx.x;           // 128 threads
    if (j < Hh) es[j] = ea[e * Hh + j];
    __syncthreads();
    float acc = b[j];
#pragma unroll
    for (int i = 0; i < Hh; i++) acc = fmaf(es[i], w[i * HID + j], acc);
    g_hid[e * HID + j] = fmaxf(acc, 0.0f);
}

// ---------------- big GEMM (tf32 tensor cores): we = hid @ W2 + b2 ----------------
// C [80000 x 4096] = A [80000 x 128] * B [128 x 4096]
#define GBM 64
#define GBN 64
#define GBK 32
#define ASTR 36
#define BSTR 68
__global__ __launch_bounds__(256, 2)
void k_gemm_we(const float* __restrict__ Bw, const float* __restrict__ bias) {
    __shared__ float As[GBM * ASTR];     // 64 x 36
    __shared__ float Bs[GBK * BSTR];     // 32 x 68
    __shared__ float Cs[GBM * BSTR];     // 64 x 68 (epilogue)

    int bn = blockIdx.x;            // 0..63  (col tile)
    int bm = blockIdx.y;            // 0..1249 (row tile)
    int t  = threadIdx.x;           // 256
    int wid = t >> 5;

    int rt = wid & 3;               // row tile 0..3 (16 rows each)
    int ct = wid >> 2;              // col half 0..1 (32 cols each)

    wmma::fragment<wmma::accumulator, 16, 16, 8, float> c0, c1;
    wmma::fill_fragment(c0, 0.0f);
    wmma::fill_fragment(c1, 0.0f);

    const float* A = g_hid + (size_t)bm * GBM * HID;
    const float* Bg = Bw + bn * GBN;

    // A-load indexing: 64 rows x 8 float4 per row = 512 float4; 2 per thread
    int a_r = t >> 3, a_c4 = (t & 7) * 4;
    // B-load indexing: 32 rows x 16 float4 per row = 512 float4; 2 per thread
    int b_r = t >> 4, b_c4 = (t & 15) * 4;

    for (int kt = 0; kt < HID; kt += GBK) {
        float4 av0 = *(const float4*)&A[a_r * HID + kt + a_c4];
        float4 av1 = *(const float4*)&A[(a_r + 32) * HID + kt + a_c4];
        *(float4*)&As[a_r * ASTR + a_c4] = av0;
        *(float4*)&As[(a_r + 32) * ASTR + a_c4] = av1;
        float4 bv0 = *(const float4*)&Bg[(size_t)(kt + b_r) * (Hh * Hh) + b_c4];
        float4 bv1 = *(const float4*)&Bg[(size_t)(kt + b_r + 16) * (Hh * Hh) + b_c4];
        *(float4*)&Bs[b_r * BSTR + b_c4] = bv0;
        *(float4*)&Bs[(b_r + 16) * BSTR + b_c4] = bv1;
        __syncthreads();
#pragma unroll
        for (int k8 = 0; k8 < GBK / 8; k8++) {
            wmma::fragment<wmma::matrix_a, 16, 16, 8, wmma::precision::tf32, wmma::row_major> af;
            wmma::fragment<wmma::matrix_b, 16, 16, 8, wmma::precision::tf32, wmma::row_major> bf0, bf1;
            wmma::load_matrix_sync(af, &As[rt * 16 * ASTR + k8 * 8], ASTR);
#pragma unroll
            for (int i = 0; i < af.num_elements; i++) af.x[i] = wmma::__float_to_tf32(af.x[i]);
            wmma::load_matrix_sync(bf0, &Bs[k8 * 8 * BSTR + ct * 32], BSTR);
            wmma::load_matrix_sync(bf1, &Bs[k8 * 8 * BSTR + ct * 32 + 16], BSTR);
#pragma unroll
            for (int i = 0; i < bf0.num_elements; i++) {
                bf0.x[i] = wmma::__float_to_tf32(bf0.x[i]);
                bf1.x[i] = wmma::__float_to_tf32(bf1.x[i]);
            }
            wmma::mma_sync(c0, af, bf0, c0);
            wmma::mma_sync(c1, af, bf1, c1);
        }
        __syncthreads();
    }

    // epilogue: acc -> smem -> (+bias) -> global
    wmma::store_matrix_sync(&Cs[rt * 16 * BSTR + ct * 32], c0, BSTR, wmma::mem_row_major);
    wmma::store_matrix_sync(&Cs[rt * 16 * BSTR + ct * 32 + 16], c1, BSTR, wmma::mem_row_major);
    __syncthreads();

    float* C = g_we + (size_t)bm * GBM * (Hh * Hh) + bn * GBN;
#pragma unroll
    for (int p = 0; p < 4; p++) {
        int idx = p * 1024 + t * 4;
        int r = idx >> 6, c = idx & 63;
        float4 v = *(float4*)&Cs[r * BSTR + c];
        int cg = bn * GBN + c;
        v.x += bias[cg + 0]; v.y += bias[cg + 1];
        v.z += bias[cg + 2]; v.w += bias[cg + 3];
        *(float4*)&C[(size_t)r * (Hh * Hh) + c] = v;
    }
}

// ---------------- degree / batch counts ----------------
__global__ void k_deg(const int* __restrict__ dst) {
    int e = blockIdx.x * blockDim.x + threadIdx.x;
    if (e < Ee) atomicAdd(&g_deg[dst[e]], 1.0f);
}
__global__ void k_cnt(const int* __restrict__ batch) {
    int n = blockIdx.x * blockDim.x + threadIdx.x;
    if (n < Nn) atomicAdd(&g_cnt[batch[n]], 1);
}
__global__ void k_scan() {
    if (threadIdx.x == 0) {
        g_ptr[0] = 0;
        for (int b = 0; b < Bb; b++) g_ptr[b + 1] = g_ptr[b] + g_cnt[b];
    }
}

// ---------------- per-edge matvec + scatter: agg[dst] += X[src] @ we[e] ----------------
// 64 threads: group g = t>>4 handles i in {g, g+4, ...}; o4 = (t&15)*4.
__global__ void k_msg(const int* __restrict__ src, const int* __restrict__ dst) {
    __shared__ float xs[Hh];
    __shared__ float red[4][Hh];
    int e = blockIdx.x, t = threadIdx.x;           // 64 threads
    int s = src[e], d = dst[e];
    xs[t] = g_X[s * Hh + t];
    __syncthreads();
    const float* we = g_we + (size_t)e * Hh * Hh;
    int g = t >> 4, o4 = (t & 15) * 4;
    float4 acc = {0.f, 0.f, 0.f, 0.f};
#pragma unroll
    for (int i = 0; i < Hh / 4; i++) {
        int ii = i * 4 + g;
        float xv = xs[ii];
        float4 w4 = *(const float4*)&we[ii * Hh + o4];
        acc.x = fmaf(xv, w4.x, acc.x);
        acc.y = fmaf(xv, w4.y, acc.y);
        acc.z = fmaf(xv, w4.z, acc.z);
        acc.w = fmaf(xv, w4.w, acc.w);
    }
    *(float4*)&red[g][o4] = acc;
    __syncthreads();
    float v = red[0][t] + red[1][t] + red[2][t] + red[3][t];
    atomicAdd(&g_agg[d * Hh + t], v);
}

// ---------------- fused m = relu(agg/deg + X@root + cb) ; X = GRU(m, X) ----------------
__global__ void k_gru(const float* __restrict__ cr, const float* __restrict__ cb,
                      const float* __restrict__ wih, const float* __restrict__ whh,
                      const float* __restrict__ bih, const float* __restrict__ bhh) {
    __shared__ float xs[Hh], ms[Hh], gi[3 * Hh], gh[3 * Hh];
    int n = blockIdx.x, t = threadIdx.x;           // 192 threads
    if (t < Hh) xs[t] = g_X[n * Hh + t];
    __syncthreads();
    if (t < Hh) {
        float d = fmaxf(g_deg[n], 1.0f);
        float acc = g_agg[n * Hh + t] / d + cb[t];
#pragma unroll
        for (int i = 0; i < Hh; i++) acc = fmaf(xs[i], cr[i * Hh + t], acc);
        ms[t] = fmaxf(acc, 0.0f);
    }
    __syncthreads();
    {
        float a = bih[t], c = bhh[t];
#pragma unroll
        for (int i = 0; i < Hh; i++) {
            a = fmaf(ms[i], wih[i * 3 * Hh + t], a);
            c = fmaf(xs[i], whh[i * 3 * Hh + t], c);
        }
        gi[t] = a; gh[t] = c;
    }
    __syncthreads();
    if (t < Hh) {
        float r = sigf(gi[t] + gh[t]);
        float z = sigf(gi[Hh + t] + gh[Hh + t]);
        float ng = tanhf(gi[2 * Hh + t] + r * gh[2 * Hh + t]);
        g_X[n * Hh + t] = (1.0f - z) * ng + z * xs[t];
    }
}

// ---------------- Set2Set LSTM step ----------------
__global__ void k_lstm(const float* __restrict__ wih, const float* __restrict__ whh,
                       const float* __restrict__ bih, const float* __restrict__ bhh) {
    __shared__ float qs[2 * Hh], hr[Hh], g[4 * Hh];
    int b = blockIdx.x, t = threadIdx.x;           // 256 threads
    if (t < 2 * Hh) qs[t] = g_qstar[b * 2 * Hh + t];
    if (t < Hh) hr[t] = g_hs[b * Hh + t];
    __syncthreads();
    {
        float a = bih[t] + bhh[t];
#pragma unroll
        for (int i = 0; i < 2 * Hh; i++) a = fmaf(qs[i], wih[i * 4 * Hh + t], a);
#pragma unroll
        for (int i = 0; i < Hh; i++) a = fmaf(hr[i], whh[i * 4 * Hh + t], a);
        g[t] = a;
    }
    __syncthreads();
    if (t < Hh) {
        float ii = sigf(g[t]);
        float ff = sigf(g[Hh + t]);
        float gg = tanhf(g[2 * Hh + t]);
        float oo = sigf(g[3 * Hh + t]);
        float c2 = ff * g_cs[b * Hh + t] + ii * gg;
        float h2 = oo * tanhf(c2);
        g_cs[b * Hh + t] = c2;
        g_hs[b * Hh + t] = h2;
        g_qstar[b * 2 * Hh + t] = h2;  // q half of q_star
    }
}

// ---------------- en[n] = dot(X[n], hs[batch[n]]) ----------------
__global__ void k_en(const int* __restrict__ batch) {
    __shared__ float red[2];
    int n = blockIdx.x, o = threadIdx.x;           // 64 threads
    int b = batch[n];
    float v = g_X[n * Hh + o] * g_hs[b * Hh + o];
#pragma unroll
    for (int s = 16; s > 0; s >>= 1) v += __shfl_down_sync(0xffffffffu, v, s);
    if ((o & 31) == 0) red[o >> 5] = v;
    __syncthreads();
    if (o == 0) g_en[n] = red[0] + red[1];
}

// ---------------- per-graph softmax + weighted readout ----------------
__global__ void k_pool() {
    __shared__ float sm[Hh];
    int b = blockIdx.x, t = threadIdx.x;           // 64 threads
    int s = g_ptr[b], e = g_ptr[b + 1];
    float m = -1e30f;
    for (int n = s + t; n < e; n += Hh) m = fmaxf(m, g_en[n]);
    sm[t] = m; __syncthreads();
    for (int st = 32; st > 0; st >>= 1) { if (t < st) sm[t] = fmaxf(sm[t], sm[t + st]); __syncthreads(); }
    float mx = sm[0]; __syncthreads();
    float ss = 0.0f;
    for (int n = s + t; n < e; n += Hh) ss += expf(g_en[n] - mx);
    sm[t] = ss; __syncthreads();
    for (int st = 32; st > 0; st >>= 1) { if (t < st) sm[t] += sm[t + st]; __syncthreads(); }
    float inv = 1.0f / (sm[0] + 1e-16f);
    float acc = 0.0f;
    for (int n = s; n < e; n++) {
        float a = expf(g_en[n] - mx) * inv;
        acc = fmaf(a, g_X[n * Hh + t], acc);
    }
    g_qstar[b * 2 * Hh + Hh + t] = acc;
}

// ---------------- head ----------------
__global__ void k_final(const float* __restrict__ w1, const float* __restrict__ b1,
                        const float* __restrict__ w2, const float* __restrict__ b2,
                        float* __restrict__ out) {
    __shared__ float qs[2 * Hh], red[Hh];
    int b = blockIdx.x, t = threadIdx.x;           // 64 threads
    qs[t] = g_qstar[b * 2 * Hh + t];
    qs[Hh + t] = g_qstar[b * 2 * Hh + Hh + t];
    __syncthreads();
    float a = b1[t];
#pragma unroll
    for (int i = 0; i < 2 * Hh; i++) a = fmaf(qs[i], w1[i * Hh + t], a);
    a = fmaxf(a, 0.0f);
    red[t] = a * w2[t];
    __syncthreads();
    for (int st = 32; st > 0; st >>= 1) { if (t < st) red[t] += red[t + st]; __syncthreads(); }
    if (t == 0) out[b] = red[0] + b2[0];
}

// ---------------- launcher ----------------
extern "C" void kernel_launch(void* const* d_in, const int* in_sizes, int n_in,
                              void* d_out, int out_size) {
    const float* x         = (const float*)d_in[0];
    const int*   ei        = (const int*)d_in[1];
    const int*   batch     = (const int*)d_in[2];
    const float* edge_attr = (const float*)d_in[3];
    const float* lin0_w = (const float*)d_in[4];
    const float* lin0_b = (const float*)d_in[5];
    const float* nn_w1  = (const float*)d_in[6];
    const float* nn_b1  = (const float*)d_in[7];
    const float* nn_w2  = (const float*)d_in[8];
    const float* nn_b2  = (const float*)d_in[9];
    const float* conv_root = (const float*)d_in[10];
    const float* conv_bias = (const float*)d_in[11];
    const float* gru_wih = (const float*)d_in[12];
    const float* gru_whh = (const float*)d_in[13];
    const float* gru_bih = (const float*)d_in[14];
    const float* gru_bhh = (const float*)d_in[15];
    const float* lstm_wih = (const float*)d_in[16];
    const float* lstm_whh = (const float*)d_in[17];
    const float* lstm_bih = (const float*)d_in[18];
    const float* lstm_bhh = (const float*)d_in[19];
    const float* lin1_w = (const float*)d_in[20];
    const float* lin1_b = (const float*)d_in[21];
    const float* lin2_w = (const float*)d_in[22];
    const float* lin2_b = (const float*)d_in[23];

    const int* src = ei;
    const int* dst = ei + Ee;

    void *p_agg, *p_deg, *p_cnt, *p_hs, *p_cs, *p_qs;
    cudaGetSymbolAddress(&p_agg, g_agg);
    cudaGetSymbolAddress(&p_deg, g_deg);
    cudaGetSymbolAddress(&p_cnt, g_cnt);
    cudaGetSymbolAddress(&p_hs,  g_hs);
    cudaGetSymbolAddress(&p_cs,  g_cs);
    cudaGetSymbolAddress(&p_qs,  g_qstar);

    cudaMemsetAsync(p_deg, 0, Nn * sizeof(float), 0);
    cudaMemsetAsync(p_cnt, 0, Bb * sizeof(int), 0);
    cudaMemsetAsync(p_hs,  0, Bb * Hh * sizeof(float), 0);
    cudaMemsetAsync(p_cs,  0, Bb * Hh * sizeof(float), 0);
    cudaMemsetAsync(p_qs,  0, Bb * 2 * Hh * sizeof(float), 0);

    k_lin0<<<Nn, Hh>>>(x, lin0_w, lin0_b);
    k_mlp1<<<Ee, HID>>>(edge_attr, nn_w1, nn_b1);
    k_gemm_we<<<dim3((Hh * Hh) / GBN, Ee / GBM), 256>>>(nn_w2, nn_b2);
    k_deg<<<(Ee + 255) / 256, 256>>>(dst);
    k_cnt<<<(Nn + 255) / 256, 256>>>(batch);
    k_scan<<<1, 32>>>();

    for (int it = 0; it < 3; it++) {
        cudaMemsetAsync(p_agg, 0, Nn * Hh * sizeof(float), 0);
        k_msg<<<Ee, Hh>>>(src, dst);
        k_gru<<<Nn, 3 * Hh>>>(conv_root, conv_bias, gru_wih, gru_whh, gru_bih, gru_bhh);
    }

    for (int st = 0; st < 3; st++) {
        k_lstm<<<Bb, 4 * Hh>>>(lstm_wih, lstm_whh, lstm_bih, lstm_bhh);
        k_en<<<Nn, Hh>>>(batch);
        k_pool<<<Bb, Hh>>>();
    }

    k_final<<<Bb, Hh>>>(lin1_w, lin1_b, lin2_w, lin2_b, (float*)d_out);
}

// round 3
// speedup vs baseline: 1.2559x; 1.1249x over previous
#include <cuda_runtime.h>
#include <cuda_fp16.h>
#include <mma.h>
#include <math.h>

using namespace nvcuda;

#define Nn  20000
#define Ee  80000
#define Hh  64
#define NFf 32
#define Bb  64
#define HID 128

// ---------------- device scratch (no allocations allowed) ----------------
__device__ float  g_X[Nn * Hh];
__device__ float  g_agg[Nn * Hh];              // zero-initialized at load; k_gru re-zeroes
__device__ float  g_hid[Ee * HID];
__device__ __half g_we[(size_t)Ee * Hh * Hh];  // 655 MB edge weights (fp16)
__device__ float  g_deg[Nn];
__device__ int    g_cnt[Bb];
__device__ int    g_ptr[Bb + 1];
__device__ float  g_en[Nn];
__device__ float  g_hs[Bb * Hh];
__device__ float  g_cs[Bb * Hh];
__device__ float  g_qstar[Bb * 2 * Hh];

__device__ __forceinline__ float sigf(float x) { return 1.0f / (1.0f + expf(-x)); }

// ---------------- lin0: X = relu(x @ W0 + b0) ----------------
__global__ void k_lin0(const float* __restrict__ x, const float* __restrict__ w,
                       const float* __restrict__ b) {
    __shared__ float xs[NFf];
    int n = blockIdx.x, o = threadIdx.x;           // 64 threads
    if (o < NFf) xs[o] = x[n * NFf + o];
    __syncthreads();
    float acc = b[o];
#pragma unroll
    for (int i = 0; i < NFf; i++) acc = fmaf(xs[i], w[i * Hh + o], acc);
    g_X[n * Hh + o] = fmaxf(acc, 0.0f);
}

// ---------------- edge MLP layer 1: hid = relu(edge_attr @ W1 + b1) ----------------
__global__ void k_mlp1(const float* __restrict__ ea, const float* __restrict__ w,
                       const float* __restrict__ b) {
    __shared__ float es[Hh];
    int e = blockIdx.x, j = threadIdx.x;           // 128 threads
    if (j < Hh) es[j] = ea[e * Hh + j];
    __syncthreads();
    float acc = b[j];
#pragma unroll
    for (int i = 0; i < Hh; i++) acc = fmaf(es[i], w[i * HID + j], acc);
    g_hid[e * HID + j] = fmaxf(acc, 0.0f);
}

// ---------------- big GEMM (tf32 tensor cores): we = fp16(hid @ W2 + b2) ----------------
#define GBM 64
#define GBN 64
#define GBK 32
#define ASTR 36
#define BSTR 68
__global__ __launch_bounds__(256, 2)
void k_gemm_we(const float* __restrict__ Bw, const float* __restrict__ bias) {
    __shared__ float As[GBM * ASTR];
    __shared__ float Bs[GBK * BSTR];
    __shared__ float Cs[GBM * BSTR];

    int bn = blockIdx.x;            // 0..63  (col tile)
    int bm = blockIdx.y;            // 0..1249 (row tile)
    int t  = threadIdx.x;           // 256
    int wid = t >> 5;

    int rt = wid & 3;               // row tile (16 rows)
    int ct = wid >> 2;              // col half (32 cols)

    wmma::fragment<wmma::accumulator, 16, 16, 8, float> c0, c1;
    wmma::fill_fragment(c0, 0.0f);
    wmma::fill_fragment(c1, 0.0f);

    const float* A = g_hid + (size_t)bm * GBM * HID;
    const float* Bg = Bw + bn * GBN;

    int a_r = t >> 3, a_c4 = (t & 7) * 4;
    int b_r = t >> 4, b_c4 = (t & 15) * 4;

    for (int kt = 0; kt < HID; kt += GBK) {
        float4 av0 = *(const float4*)&A[a_r * HID + kt + a_c4];
        float4 av1 = *(const float4*)&A[(a_r + 32) * HID + kt + a_c4];
        *(float4*)&As[a_r * ASTR + a_c4] = av0;
        *(float4*)&As[(a_r + 32) * ASTR + a_c4] = av1;
        float4 bv0 = *(const float4*)&Bg[(size_t)(kt + b_r) * (Hh * Hh) + b_c4];
        float4 bv1 = *(const float4*)&Bg[(size_t)(kt + b_r + 16) * (Hh * Hh) + b_c4];
        *(float4*)&Bs[b_r * BSTR + b_c4] = bv0;
        *(float4*)&Bs[(b_r + 16) * BSTR + b_c4] = bv1;
        __syncthreads();
#pragma unroll
        for (int k8 = 0; k8 < GBK / 8; k8++) {
            wmma::fragment<wmma::matrix_a, 16, 16, 8, wmma::precision::tf32, wmma::row_major> af;
            wmma::fragment<wmma::matrix_b, 16, 16, 8, wmma::precision::tf32, wmma::row_major> bf0, bf1;
            wmma::load_matrix_sync(af, &As[rt * 16 * ASTR + k8 * 8], ASTR);
#pragma unroll
            for (int i = 0; i < af.num_elements; i++) af.x[i] = wmma::__float_to_tf32(af.x[i]);
            wmma::load_matrix_sync(bf0, &Bs[k8 * 8 * BSTR + ct * 32], BSTR);
            wmma::load_matrix_sync(bf1, &Bs[k8 * 8 * BSTR + ct * 32 + 16], BSTR);
#pragma unroll
            for (int i = 0; i < bf0.num_elements; i++) {
                bf0.x[i] = wmma::__float_to_tf32(bf0.x[i]);
                bf1.x[i] = wmma::__float_to_tf32(bf1.x[i]);
            }
            wmma::mma_sync(c0, af, bf0, c0);
            wmma::mma_sync(c1, af, bf1, c1);
        }
        __syncthreads();
    }

    wmma::store_matrix_sync(&Cs[rt * 16 * BSTR + ct * 32], c0, BSTR, wmma::mem_row_major);
    wmma::store_matrix_sync(&Cs[rt * 16 * BSTR + ct * 32 + 16], c1, BSTR, wmma::mem_row_major);
    __syncthreads();

    __half* C = g_we + (size_t)bm * GBM * (Hh * Hh) + bn * GBN;
#pragma unroll
    for (int p = 0; p < 4; p++) {
        int idx = p * 1024 + t * 4;
        int r = idx >> 6, c = idx & 63;
        float4 v = *(float4*)&Cs[r * BSTR + c];
        int cg = bn * GBN + c;
        v.x += bias[cg + 0]; v.y += bias[cg + 1];
        v.z += bias[cg + 2]; v.w += bias[cg + 3];
        __half2 h0 = __floats2half2_rn(v.x, v.y);
        __half2 h1 = __floats2half2_rn(v.z, v.w);
        *(__half2*)&C[(size_t)r * (Hh * Hh) + c] = h0;
        *(__half2*)&C[(size_t)r * (Hh * Hh) + c + 2] = h1;
    }
}

// ---------------- degree / batch counts ----------------
__global__ void k_deg(const int* __restrict__ dst) {
    int e = blockIdx.x * blockDim.x + threadIdx.x;
    if (e < Ee) atomicAdd(&g_deg[dst[e]], 1.0f);
}
__global__ void k_cnt(const int* __restrict__ batch) {
    int n = blockIdx.x * blockDim.x + threadIdx.x;
    if (n < Nn) atomicAdd(&g_cnt[batch[n]], 1);
}
__global__ void k_scan() {
    if (threadIdx.x == 0) {
        g_ptr[0] = 0;
        for (int b = 0; b < Bb; b++) g_ptr[b + 1] = g_ptr[b] + g_cnt[b];
    }
}

// ---------------- per-edge matvec + scatter: agg[dst] += X[src] @ we[e] ----------------
__global__ void k_msg(const int* __restrict__ src, const int* __restrict__ dst) {
    __shared__ float xs[Hh];
    __shared__ float red[4][Hh];
    int e = blockIdx.x, t = threadIdx.x;           // 64 threads
    int s = src[e], d = dst[e];
    xs[t] = g_X[s * Hh + t];
    __syncthreads();
    const __half* we = g_we + (size_t)e * Hh * Hh;
    int g = t >> 4, c4 = (t & 15) * 4;
    float4 acc = {0.f, 0.f, 0.f, 0.f};
#pragma unroll
    for (int i = 0; i < Hh / 4; i++) {
        int ii = i * 4 + g;
        float xv = xs[ii];
        __half2 h01 = *(const __half2*)&we[ii * Hh + c4];
        __half2 h23 = *(const __half2*)&we[ii * Hh + c4 + 2];
        float2 f01 = __half22float2(h01);
        float2 f23 = __half22float2(h23);
        acc.x = fmaf(xv, f01.x, acc.x);
        acc.y = fmaf(xv, f01.y, acc.y);
        acc.z = fmaf(xv, f23.x, acc.z);
        acc.w = fmaf(xv, f23.y, acc.w);
    }
    *(float4*)&red[g][c4] = acc;
    __syncthreads();
    float v = red[0][t] + red[1][t] + red[2][t] + red[3][t];
    atomicAdd(&g_agg[d * Hh + t], v);
}

// ---------------- fused m = relu(agg/deg + X@root + cb) ; X = GRU(m, X) ----------------
// also re-zeroes g_agg for the next iteration (replaces memset)
__global__ void k_gru(const float* __restrict__ cr, const float* __restrict__ cb,
                      const float* __restrict__ wih, const float* __restrict__ whh,
                      const float* __restrict__ bih, const float* __restrict__ bhh) {
    __shared__ float xs[Hh], ms[Hh], gi[3 * Hh], gh[3 * Hh];
    int n = blockIdx.x, t = threadIdx.x;           // 192 threads
    if (t < Hh) xs[t] = g_X[n * Hh + t];
    __syncthreads();
    if (t < Hh) {
        float d = fmaxf(g_deg[n], 1.0f);
        float acc = g_agg[n * Hh + t] / d + cb[t];
        g_agg[n * Hh + t] = 0.0f;                  // reset for next iter / next call
#pragma unroll
        for (int i = 0; i < Hh; i++) acc = fmaf(xs[i], cr[i * Hh + t], acc);
        ms[t] = fmaxf(acc, 0.0f);
    }
    __syncthreads();
    {
        float a = bih[t], c = bhh[t];
#pragma unroll
        for (int i = 0; i < Hh; i++) {
            a = fmaf(ms[i], wih[i * 3 * Hh + t], a);
            c = fmaf(xs[i], whh[i * 3 * Hh + t], c);
        }
        gi[t] = a; gh[t] = c;
    }
    __syncthreads();
    if (t < Hh) {
        float r = sigf(gi[t] + gh[t]);
        float z = sigf(gi[Hh + t] + gh[Hh + t]);
        float ng = tanhf(gi[2 * Hh + t] + r * gh[2 * Hh + t]);
        g_X[n * Hh + t] = (1.0f - z) * ng + z * xs[t];
    }
}

// ---------------- Set2Set LSTM step ----------------
__global__ void k_lstm(const float* __restrict__ wih, const float* __restrict__ whh,
                       const float* __restrict__ bih, const float* __restrict__ bhh) {
    __shared__ float qs[2 * Hh], hr[Hh], g[4 * Hh];
    int b = blockIdx.x, t = threadIdx.x;           // 256 threads
    if (t < 2 * Hh) qs[t] = g_qstar[b * 2 * Hh + t];
    if (t < Hh) hr[t] = g_hs[b * Hh + t];
    __syncthreads();
    {
        float a = bih[t] + bhh[t];
#pragma unroll
        for (int i = 0; i < 2 * Hh; i++) a = fmaf(qs[i], wih[i * 4 * Hh + t], a);
#pragma unroll
        for (int i = 0; i < Hh; i++) a = fmaf(hr[i], whh[i * 4 * Hh + t], a);
        g[t] = a;
    }
    __syncthreads();
    if (t < Hh) {
        float ii = sigf(g[t]);
        float ff = sigf(g[Hh + t]);
        float gg = tanhf(g[2 * Hh + t]);
        float oo = sigf(g[3 * Hh + t]);
        float c2 = ff * g_cs[b * Hh + t] + ii * gg;
        float h2 = oo * tanhf(c2);
        g_cs[b * Hh + t] = c2;
        g_hs[b * Hh + t] = h2;
        g_qstar[b * 2 * Hh + t] = h2;
    }
}

// ---------------- en[n] = dot(X[n], hs[batch[n]]) ----------------
__global__ void k_en(const int* __restrict__ batch) {
    __shared__ float red[2];
    int n = blockIdx.x, o = threadIdx.x;           // 64 threads
    int b = batch[n];
    float v = g_X[n * Hh + o] * g_hs[b * Hh + o];
#pragma unroll
    for (int s = 16; s > 0; s >>= 1) v += __shfl_down_sync(0xffffffffu, v, s);
    if ((o & 31) == 0) red[o >> 5] = v;
    __syncthreads();
    if (o == 0) g_en[n] = red[0] + red[1];
}

// ---------------- per-graph softmax + weighted readout ----------------
__global__ void k_pool() {
    __shared__ float sm[Hh];
    int b = blockIdx.x, t = threadIdx.x;           // 64 threads
    int s = g_ptr[b], e = g_ptr[b + 1];
    float m = -1e30f;
    for (int n = s + t; n < e; n += Hh) m = fmaxf(m, g_en[n]);
    sm[t] = m; __syncthreads();
    for (int st = 32; st > 0; st >>= 1) { if (t < st) sm[t] = fmaxf(sm[t], sm[t + st]); __syncthreads(); }
    float mx = sm[0]; __syncthreads();
    float ss = 0.0f;
    for (int n = s + t; n < e; n += Hh) ss += expf(g_en[n] - mx);
    sm[t] = ss; __syncthreads();
    for (int st = 32; st > 0; st >>= 1) { if (t < st) sm[t] += sm[t + st]; __syncthreads(); }
    float inv = 1.0f / (sm[0] + 1e-16f);
    float acc = 0.0f;
    for (int n = s; n < e; n++) {
        float a = expf(g_en[n] - mx) * inv;
        acc = fmaf(a, g_X[n * Hh + t], acc);
    }
    g_qstar[b * 2 * Hh + Hh + t] = acc;
}

// ---------------- head ----------------
__global__ void k_final(const float* __restrict__ w1, const float* __restrict__ b1,
                        const float* __restrict__ w2, const float* __restrict__ b2,
                        float* __restrict__ out) {
    __shared__ float qs[2 * Hh], red[Hh];
    int b = blockIdx.x, t = threadIdx.x;           // 64 threads
    qs[t] = g_qstar[b * 2 * Hh + t];
    qs[Hh + t] = g_qstar[b * 2 * Hh + Hh + t];
    __syncthreads();
    float a = b1[t];
#pragma unroll
    for (int i = 0; i < 2 * Hh; i++) a = fmaf(qs[i], w1[i * Hh + t], a);
    a = fmaxf(a, 0.0f);
    red[t] = a * w2[t];
    __syncthreads();
    for (int st = 32; st > 0; st >>= 1) { if (t < st) red[t] += red[t + st]; __syncthreads(); }
    if (t == 0) out[b] = red[0] + b2[0];
}

// ---------------- launcher ----------------
extern "C" void kernel_launch(void* const* d_in, const int* in_sizes, int n_in,
                              void* d_out, int out_size) {
    const float* x         = (const float*)d_in[0];
    const int*   ei        = (const int*)d_in[1];
    const int*   batch     = (const int*)d_in[2];
    const float* edge_attr = (const float*)d_in[3];
    const float* lin0_w = (const float*)d_in[4];
    const float* lin0_b = (const float*)d_in[5];
    const float* nn_w1  = (const float*)d_in[6];
    const float* nn_b1  = (const float*)d_in[7];
    const float* nn_w2  = (const float*)d_in[8];
    const float* nn_b2  = (const float*)d_in[9];
    const float* conv_root = (const float*)d_in[10];
    const float* conv_bias = (const float*)d_in[11];
    const float* gru_wih = (const float*)d_in[12];
    const float* gru_whh = (const float*)d_in[13];
    const float* gru_bih = (const float*)d_in[14];
    const float* gru_bhh = (const float*)d_in[15];
    const float* lstm_wih = (const float*)d_in[16];
    const float* lstm_whh = (const float*)d_in[17];
    const float* lstm_bih = (const float*)d_in[18];
    const float* lstm_bhh = (const float*)d_in[19];
    const float* lin1_w = (const float*)d_in[20];
    const float* lin1_b = (const float*)d_in[21];
    const float* lin2_w = (const float*)d_in[22];
    const float* lin2_b = (const float*)d_in[23];

    const int* src = ei;
    const int* dst = ei + Ee;

    void *p_deg, *p_cnt, *p_hs, *p_cs, *p_qs;
    cudaGetSymbolAddress(&p_deg, g_deg);
    cudaGetSymbolAddress(&p_cnt, g_cnt);
    cudaGetSymbolAddress(&p_hs,  g_hs);
    cudaGetSymbolAddress(&p_cs,  g_cs);
    cudaGetSymbolAddress(&p_qs,  g_qstar);

    cudaMemsetAsync(p_deg, 0, Nn * sizeof(float), 0);
    cudaMemsetAsync(p_cnt, 0, Bb * sizeof(int), 0);
    cudaMemsetAsync(p_hs,  0, Bb * Hh * sizeof(float), 0);
    cudaMemsetAsync(p_cs,  0, Bb * Hh * sizeof(float), 0);
    cudaMemsetAsync(p_qs,  0, Bb * 2 * Hh * sizeof(float), 0);

    // order chosen so the ncu -s window lands on k_gemm_we next round
    k_lin0<<<Nn, Hh>>>(x, lin0_w, lin0_b);
    k_mlp1<<<Ee, HID>>>(edge_attr, nn_w1, nn_b1);
    k_deg<<<(Ee + 255) / 256, 256>>>(dst);
    k_gemm_we<<<dim3((Hh * Hh) / GBN, Ee / GBM), 256>>>(nn_w2, nn_b2);
    k_cnt<<<(Nn + 255) / 256, 256>>>(batch);
    k_scan<<<1, 32>>>();

    for (int it = 0; it < 3; it++) {
        k_msg<<<Ee, Hh>>>(src, dst);
        k_gru<<<Nn, 3 * Hh>>>(conv_root, conv_bias, gru_wih, gru_whh, gru_bih, gru_bhh);
    }

    for (int st = 0; st < 3; st++) {
        k_lstm<<<Bb, 4 * Hh>>>(lstm_wih, lstm_whh, lstm_bih, lstm_bhh);
        k_en<<<Nn, Hh>>>(batch);
        k_pool<<<Bb, Hh>>>();
    }

    k_final<<<Bb, Hh>>>(lin1_w, lin1_b, lin2_w, lin2_b, (float*)d_out);
}

// round 4
// speedup vs baseline: 2.2627x; 1.8017x over previous
#include <cuda_runtime.h>
#include <cuda_fp16.h>
#include <mma.h>
#include <math.h>

using namespace nvcuda;

#define Nn  20000
#define Ee  80000
#define Hh  64
#define NFf 32
#define Bb  64
#define HID 128

// ---------------- device scratch (no allocations allowed) ----------------
__device__ float  g_X[Nn * Hh];
__device__ float  g_agg[Nn * Hh];              // zeroed at load; k_gru re-zeroes after use
__device__ __half g_hid[Ee * HID];             // edge MLP hidden (fp16)
__device__ __half g_w2h[HID * Hh * Hh];        // W2 in fp16 (1 MB)
__device__ __half g_we[(size_t)Ee * Hh * Hh];  // 655 MB edge weights (fp16)
__device__ float  g_deg[Nn];
__device__ int    g_cnt[Bb];
__device__ int    g_ptr[Bb + 1];
__device__ float  g_en[Nn];
__device__ float  g_hs[Bb * Hh];
__device__ float  g_cs[Bb * Hh];
__device__ float  g_qstar[Bb * 2 * Hh];

__device__ __forceinline__ float sigf(float x) { return 1.0f / (1.0f + expf(-x)); }

// ---------------- prep: W2 -> fp16 ----------------
__global__ void k_prep(const float* __restrict__ w2) {
    int i4 = (blockIdx.x * 256 + threadIdx.x) * 4;   // 512 blocks x 256 thr x 4
    float4 v = *(const float4*)&w2[i4];
    __half2 h0 = __floats2half2_rn(v.x, v.y);
    __half2 h1 = __floats2half2_rn(v.z, v.w);
    *(__half2*)&g_w2h[i4] = h0;
    *(__half2*)&g_w2h[i4 + 2] = h1;
}

// ---------------- lin0: X = relu(x @ W0 + b0) ----------------
__global__ void k_lin0(const float* __restrict__ x, const float* __restrict__ w,
                       const float* __restrict__ b) {
    __shared__ float xs[NFf];
    int n = blockIdx.x, o = threadIdx.x;           // 64 threads
    if (o < NFf) xs[o] = x[n * NFf + o];
    __syncthreads();
    float acc = b[o];
#pragma unroll
    for (int i = 0; i < NFf; i++) acc = fmaf(xs[i], w[i * Hh + o], acc);
    g_X[n * Hh + o] = fmaxf(acc, 0.0f);
}

// ---------------- edge MLP layer 1: hid = fp16(relu(edge_attr @ W1 + b1)) ----------------
__global__ void k_mlp1(const float* __restrict__ ea, const float* __restrict__ w,
                       const float* __restrict__ b) {
    __shared__ float es[Hh];
    int e = blockIdx.x, j = threadIdx.x;           // 128 threads
    if (j < Hh) es[j] = ea[e * Hh + j];
    __syncthreads();
    float acc = b[j];
#pragma unroll
    for (int i = 0; i < Hh; i++) acc = fmaf(es[i], w[i * HID + j], acc);
    g_hid[e * HID + j] = __float2half_rn(fmaxf(acc, 0.0f));
}

// ---------------- big GEMM (fp16 HMMA): we = fp16(hid @ W2 + b2) ----------------
// C [80000 x 4096] = A [80000 x 128](h) * B [128 x 4096](h), fp32 accum
#define GBM 64
#define GBN 64
#define GBK 64
#define HSTR 72
#define BSTRc 68
__global__ __launch_bounds__(256)
void k_gemm_we(const float* __restrict__ bias) {
    __shared__ __half As[GBM * HSTR];     // 64 x 72 half
    __shared__ __half Bs[GBK * HSTR];     // 64 x 72 half
    __shared__ float  Cs[GBM * BSTRc];    // 64 x 68 float (epilogue)

    int bn = blockIdx.x;            // 0..63  (col tile)
    int bm = blockIdx.y;            // 0..1249 (row tile)
    int t  = threadIdx.x;           // 256
    int wid = t >> 5;
    int rt = wid & 3;               // 16-row tile
    int ct = wid >> 2;              // 32-col half

    wmma::fragment<wmma::accumulator, 16, 16, 16, float> c0, c1;
    wmma::fill_fragment(c0, 0.0f);
    wmma::fill_fragment(c1, 0.0f);

    const __half* A = g_hid + (size_t)bm * GBM * HID;
    const __half* Bg = g_w2h + bn * GBN;

    int lr = t >> 3;                // 0..31
    int lc = (t & 7) * 8;           // half-index 0..56, 8 halfs = 16B

    for (int kt = 0; kt < HID; kt += GBK) {
        *(float4*)&As[lr * HSTR + lc]        = *(const float4*)&A[lr * HID + kt + lc];
        *(float4*)&As[(lr + 32) * HSTR + lc] = *(const float4*)&A[(lr + 32) * HID + kt + lc];
        *(float4*)&Bs[lr * HSTR + lc]        = *(const float4*)&Bg[(size_t)(kt + lr) * (Hh * Hh) + lc];
        *(float4*)&Bs[(lr + 32) * HSTR + lc] = *(const float4*)&Bg[(size_t)(kt + lr + 32) * (Hh * Hh) + lc];
        __syncthreads();
#pragma unroll
        for (int k16 = 0; k16 < GBK / 16; k16++) {
            wmma::fragment<wmma::matrix_a, 16, 16, 16, __half, wmma::row_major> af;
            wmma::fragment<wmma::matrix_b, 16, 16, 16, __half, wmma::row_major> bf0, bf1;
            wmma::load_matrix_sync(af, &As[rt * 16 * HSTR + k16 * 16], HSTR);
            wmma::load_matrix_sync(bf0, &Bs[k16 * 16 * HSTR + ct * 32], HSTR);
            wmma::load_matrix_sync(bf1, &Bs[k16 * 16 * HSTR + ct * 32 + 16], HSTR);
            wmma::mma_sync(c0, af, bf0, c0);
            wmma::mma_sync(c1, af, bf1, c1);
        }
        __syncthreads();
    }

    wmma::store_matrix_sync(&Cs[rt * 16 * BSTRc + ct * 32], c0, BSTRc, wmma::mem_row_major);
    wmma::store_matrix_sync(&Cs[rt * 16 * BSTRc + ct * 32 + 16], c1, BSTRc, wmma::mem_row_major);
    __syncthreads();

    __half* C = g_we + (size_t)bm * GBM * (Hh * Hh) + bn * GBN;
#pragma unroll
    for (int p = 0; p < 4; p++) {
        int idx = p * 1024 + t * 4;
        int r = idx >> 6, c = idx & 63;
        float4 v = *(float4*)&Cs[r * BSTRc + c];
        int cg = bn * GBN + c;
        v.x += bias[cg + 0]; v.y += bias[cg + 1];
        v.z += bias[cg + 2]; v.w += bias[cg + 3];
        __half2 h0 = __floats2half2_rn(v.x, v.y);
        __half2 h1 = __floats2half2_rn(v.z, v.w);
        *(__half2*)&C[(size_t)r * (Hh * Hh) + c] = h0;
        *(__half2*)&C[(size_t)r * (Hh * Hh) + c + 2] = h1;
    }
}

// ---------------- degree / batch counts ----------------
__global__ void k_deg(const int* __restrict__ dst) {
    int e = blockIdx.x * blockDim.x + threadIdx.x;
    if (e < Ee) atomicAdd(&g_deg[dst[e]], 1.0f);
}
__global__ void k_cnt(const int* __restrict__ batch) {
    int n = blockIdx.x * blockDim.x + threadIdx.x;
    if (n < Nn) atomicAdd(&g_cnt[batch[n]], 1);
}
// scan + zero LSTM/Set2Set state
__global__ void k_scan() {
    int t = threadIdx.x;           // 256 threads
    if (t == 0) {
        g_ptr[0] = 0;
        for (int b = 0; b < Bb; b++) g_ptr[b + 1] = g_ptr[b] + g_cnt[b];
    }
    for (int i = t; i < Bb * Hh; i += 256) { g_hs[i] = 0.0f; g_cs[i] = 0.0f; }
    for (int i = t; i < Bb * 2 * Hh; i += 256) g_qstar[i] = 0.0f;
}

// ---------------- per-edge matvec + scatter: 4 edges per block ----------------
__global__ __launch_bounds__(256)
void k_msg(const int* __restrict__ src, const int* __restrict__ dst) {
    __shared__ float xs[4][Hh];
    __shared__ float red[4][4][Hh];
    int t = threadIdx.x;                    // 256
    int le = t >> 6;                        // local edge 0..3
    int u  = t & 63;                        // lane within edge
    int e  = blockIdx.x * 4 + le;
    int s = src[e], d = dst[e];
    xs[le][u] = g_X[s * Hh + u];
    __syncthreads();
    const __half* we = g_we + (size_t)e * Hh * Hh;
    int g = u >> 4, c4 = (u & 15) * 4;
    float4 acc = {0.f, 0.f, 0.f, 0.f};
#pragma unroll
    for (int i = 0; i < Hh / 4; i++) {
        int ii = i * 4 + g;
        float xv = xs[le][ii];
        __half2 h01 = *(const __half2*)&we[ii * Hh + c4];
        __half2 h23 = *(const __half2*)&we[ii * Hh + c4 + 2];
        float2 f01 = __half22float2(h01);
        float2 f23 = __half22float2(h23);
        acc.x = fmaf(xv, f01.x, acc.x);
        acc.y = fmaf(xv, f01.y, acc.y);
        acc.z = fmaf(xv, f23.x, acc.z);
        acc.w = fmaf(xv, f23.y, acc.w);
    }
    *(float4*)&red[le][g][c4] = acc;
    __syncthreads();
    float v = red[le][0][u] + red[le][1][u] + red[le][2][u] + red[le][3][u];
    atomicAdd(&g_agg[d * Hh + u], v);
}

// ---------------- fused m = relu(agg/deg + X@root + cb) ; X = GRU(m, X) ----------------
__global__ void k_gru(const float* __restrict__ cr, const float* __restrict__ cb,
                      const float* __restrict__ wih, const float* __restrict__ whh,
                      const float* __restrict__ bih, const float* __restrict__ bhh) {
    __shared__ float xs[Hh], ms[Hh], gi[3 * Hh], gh[3 * Hh];
    int n = blockIdx.x, t = threadIdx.x;           // 192 threads
    if (t < Hh) xs[t] = g_X[n * Hh + t];
    __syncthreads();
    if (t < Hh) {
        float d = fmaxf(g_deg[n], 1.0f);
        float acc = g_agg[n * Hh + t] / d + cb[t];
        g_agg[n * Hh + t] = 0.0f;
#pragma unroll
        for (int i = 0; i < Hh; i++) acc = fmaf(xs[i], cr[i * Hh + t], acc);
        ms[t] = fmaxf(acc, 0.0f);
    }
    __syncthreads();
    {
        float a = bih[t], c = bhh[t];
#pragma unroll
        for (int i = 0; i < Hh; i++) {
            a = fmaf(ms[i], wih[i * 3 * Hh + t], a);
            c = fmaf(xs[i], whh[i * 3 * Hh + t], c);
        }
        gi[t] = a; gh[t] = c;
    }
    __syncthreads();
    if (t < Hh) {
        float r = sigf(gi[t] + gh[t]);
        float z = sigf(gi[Hh + t] + gh[Hh + t]);
        float ng = tanhf(gi[2 * Hh + t] + r * gh[2 * Hh + t]);
        g_X[n * Hh + t] = (1.0f - z) * ng + z * xs[t];
    }
}

// ---------------- Set2Set LSTM step ----------------
__global__ void k_lstm(const float* __restrict__ wih, const float* __restrict__ whh,
                       const float* __restrict__ bih, const float* __restrict__ bhh) {
    __shared__ float qs[2 * Hh], hr[Hh], g[4 * Hh];
    int b = blockIdx.x, t = threadIdx.x;           // 256 threads
    if (t < 2 * Hh) qs[t] = g_qstar[b * 2 * Hh + t];
    if (t < Hh) hr[t] = g_hs[b * Hh + t];
    __syncthreads();
    {
        float a = bih[t] + bhh[t];
#pragma unroll
        for (int i = 0; i < 2 * Hh; i++) a = fmaf(qs[i], wih[i * 4 * Hh + t], a);
#pragma unroll
        for (int i = 0; i < Hh; i++) a = fmaf(hr[i], whh[i * 4 * Hh + t], a);
        g[t] = a;
    }
    __syncthreads();
    if (t < Hh) {
        float ii = sigf(g[t]);
        float ff = sigf(g[Hh + t]);
        float gg = tanhf(g[2 * Hh + t]);
        float oo = sigf(g[3 * Hh + t]);
        float c2 = ff * g_cs[b * Hh + t] + ii * gg;
        float h2 = oo * tanhf(c2);
        g_cs[b * Hh + t] = c2;
        g_hs[b * Hh + t] = h2;
        g_qstar[b * 2 * Hh + t] = h2;
    }
}

// ---------------- en[n] = dot(X[n], hs[batch[n]]) ----------------
__global__ void k_en(const int* __restrict__ batch) {
    __shared__ float red[2];
    int n = blockIdx.x, o = threadIdx.x;           // 64 threads
    int b = batch[n];
    float v = g_X[n * Hh + o] * g_hs[b * Hh + o];
#pragma unroll
    for (int s = 16; s > 0; s >>= 1) v += __shfl_down_sync(0xffffffffu, v, s);
    if ((o & 31) == 0) red[o >> 5] = v;
    __syncthreads();
    if (o == 0) g_en[n] = red[0] + red[1];
}

// ---------------- per-graph softmax + weighted readout ----------------
__global__ void k_pool() {
    __shared__ float sm[Hh];
    int b = blockIdx.x, t = threadIdx.x;           // 64 threads
    int s = g_ptr[b], e = g_ptr[b + 1];
    float m = -1e30f;
    for (int n = s + t; n < e; n += Hh) m = fmaxf(m, g_en[n]);
    sm[t] = m; __syncthreads();
    for (int st = 32; st > 0; st >>= 1) { if (t < st) sm[t] = fmaxf(sm[t], sm[t + st]); __syncthreads(); }
    float mx = sm[0]; __syncthreads();
    float ss = 0.0f;
    for (int n = s + t; n < e; n += Hh) ss += expf(g_en[n] - mx);
    sm[t] = ss; __syncthreads();
    for (int st = 32; st > 0; st >>= 1) { if (t < st) sm[t] += sm[t + st]; __syncthreads(); }
    float inv = 1.0f / (sm[0] + 1e-16f);
    float acc = 0.0f;
    for (int n = s; n < e; n++) {
        float a = expf(g_en[n] - mx) * inv;
        acc = fmaf(a, g_X[n * Hh + t], acc);
    }
    g_qstar[b * 2 * Hh + Hh + t] = acc;
}

// ---------------- head ----------------
__global__ void k_final(const float* __restrict__ w1, const float* __restrict__ b1,
                        const float* __restrict__ w2, const float* __restrict__ b2,
                        float* __restrict__ out) {
    __shared__ float qs[2 * Hh], red[Hh];
    int b = blockIdx.x, t = threadIdx.x;           // 64 threads
    qs[t] = g_qstar[b * 2 * Hh + t];
    qs[Hh + t] = g_qstar[b * 2 * Hh + Hh + t];
    __syncthreads();
    float a = b1[t];
#pragma unroll
    for (int i = 0; i < 2 * Hh; i++) a = fmaf(qs[i], w1[i * Hh + t], a);
    a = fmaxf(a, 0.0f);
    red[t] = a * w2[t];
    __syncthreads();
    for (int st = 32; st > 0; st >>= 1) { if (t < st) red[t] += red[t + st]; __syncthreads(); }
    if (t == 0) out[b] = red[0] + b2[0];
}

// ---------------- launcher ----------------
extern "C" void kernel_launch(void* const* d_in, const int* in_sizes, int n_in,
                              void* d_out, int out_size) {
    const float* x         = (const float*)d_in[0];
    const int*   ei        = (const int*)d_in[1];
    const int*   batch     = (const int*)d_in[2];
    const float* edge_attr = (const float*)d_in[3];
    const float* lin0_w = (const float*)d_in[4];
    const float* lin0_b = (const float*)d_in[5];
    const float* nn_w1  = (const float*)d_in[6];
    const float* nn_b1  = (const float*)d_in[7];
    const float* nn_w2  = (const float*)d_in[8];
    const float* nn_b2  = (const float*)d_in[9];
    const float* conv_root = (const float*)d_in[10];
    const float* conv_bias = (const float*)d_in[11];
    const float* gru_wih = (const float*)d_in[12];
    const float* gru_whh = (const float*)d_in[13];
    const float* gru_bih = (const float*)d_in[14];
    const float* gru_bhh = (const float*)d_in[15];
    const float* lstm_wih = (const float*)d_in[16];
    const float* lstm_whh = (const float*)d_in[17];
    const float* lstm_bih = (const float*)d_in[18];
    const float* lstm_bhh = (const float*)d_in[19];
    const float* lin1_w = (const float*)d_in[20];
    const float* lin1_b = (const float*)d_in[21];
    const float* lin2_w = (const float*)d_in[22];
    const float* lin2_b = (const float*)d_in[23];

    const int* src = ei;
    const int* dst = ei + Ee;

    void *p_deg, *p_cnt;
    cudaGetSymbolAddress(&p_deg, g_deg);
    cudaGetSymbolAddress(&p_cnt, g_cnt);
    cudaMemsetAsync(p_deg, 0, Nn * sizeof(float), 0);
    cudaMemsetAsync(p_cnt, 0, Bb * sizeof(int), 0);

    // kernel launch order: #4 (k_gemm_we) is the ncu-profiled launch
    k_prep<<<512, 256>>>(nn_w2);                                     // 1
    k_lin0<<<Nn, Hh>>>(x, lin0_w, lin0_b);                           // 2
    k_mlp1<<<Ee, HID>>>(edge_attr, nn_w1, nn_b1);                    // 3
    k_gemm_we<<<dim3((Hh * Hh) / GBN, Ee / GBM), 256>>>(nn_b2);      // 4 <- profiled
    k_deg<<<(Ee + 255) / 256, 256>>>(dst);                           // 5
    k_cnt<<<(Nn + 255) / 256, 256>>>(batch);                         // 6
    k_scan<<<1, 256>>>();                                            // 7

    for (int it = 0; it < 3; it++) {
        k_msg<<<Ee / 4, 256>>>(src, dst);
        k_gru<<<Nn, 3 * Hh>>>(conv_root, conv_bias, gru_wih, gru_whh, gru_bih, gru_bhh);
    }

    for (int st = 0; st < 3; st++) {
        k_lstm<<<Bb, 4 * Hh>>>(lstm_wih, lstm_whh, lstm_bih, lstm_bhh);
        k_en<<<Nn, Hh>>>(batch);
        k_pool<<<Bb, Hh>>>();
    }

    k_final<<<Bb, Hh>>>(lin1_w, lin1_b, lin2_w, lin2_b, (float*)d_out);
}